// round 2
// baseline (speedup 1.0000x reference)
#include <cuda_runtime.h>

#define BB 2
#define MM 4096
#define NN 16384
#define CC 256
#define KK 3

// Scratch (no cudaMalloc allowed): 8MB p1 transposed + knn results
__device__ float g_p1t[BB * MM * CC];   // [b][m][c] layout for contiguous gather
__device__ int   g_idx[BB * NN * KK];
__device__ float g_wgt[BB * NN * KK];

// ---------------------------------------------------------------------------
// kNN: for each query n in xyz_2, find 3 nearest points in xyz_1 (M=4096).
// All of xyz_1 (48KB) fits in static shared memory. One thread per query.
// ---------------------------------------------------------------------------
__global__ void knn_kernel(const float* __restrict__ xyz1,
                           const float* __restrict__ xyz2) {
    __shared__ float sx[MM];
    __shared__ float sy[MM];
    __shared__ float sz[MM];
    const int b = blockIdx.y;
    for (int t = threadIdx.x; t < MM; t += 256) {
        sx[t] = xyz1[(b * 3 + 0) * MM + t];
        sy[t] = xyz1[(b * 3 + 1) * MM + t];
        sz[t] = xyz1[(b * 3 + 2) * MM + t];
    }
    __syncthreads();

    const int n = blockIdx.x * 256 + threadIdx.x;
    const float qx = xyz2[(b * 3 + 0) * NN + n];
    const float qy = xyz2[(b * 3 + 1) * NN + n];
    const float qz = xyz2[(b * 3 + 2) * NN + n];

    float d0 = 3.4e38f, d1 = 3.4e38f, d2 = 3.4e38f;
    int   i0 = 0, i1 = 0, i2 = 0;

    #pragma unroll 4
    for (int m = 0; m < MM; m++) {
        const float dx = sx[m] - qx;
        const float dy = sy[m] - qy;
        const float dz = sz[m] - qz;
        const float d = fmaf(dx, dx, fmaf(dy, dy, dz * dz));
        if (d < d2) {
            if (d < d1) {
                if (d < d0) { d2 = d1; i2 = i1; d1 = d0; i1 = i0; d0 = d; i0 = m; }
                else        { d2 = d1; i2 = i1; d1 = d;  i1 = m; }
            } else          { d2 = d;  i2 = m; }
        }
    }

    const float r0 = 1.0f / (d0 + 1e-8f);
    const float r1 = 1.0f / (d1 + 1e-8f);
    const float r2 = 1.0f / (d2 + 1e-8f);
    const float s = 1.0f / (r0 + r1 + r2);
    const int base = (b * NN + n) * KK;
    g_idx[base + 0] = i0; g_idx[base + 1] = i1; g_idx[base + 2] = i2;
    g_wgt[base + 0] = r0 * s; g_wgt[base + 1] = r1 * s; g_wgt[base + 2] = r2 * s;
}

// ---------------------------------------------------------------------------
// GEMM1: p1t[b][m][o] = sum_c w1[o][c] * points_1[b][c][m] + b1[o]
// 64x64 tile, 256 threads, 4x4 per thread, K-chunk 16. Output stored
// TRANSPOSED (m-major, o contiguous) so the interp gather reads float4s.
// ---------------------------------------------------------------------------
__global__ void gemm1_kernel(const float* __restrict__ w1,
                             const float* __restrict__ b1,
                             const float* __restrict__ p1in) {
    __shared__ float As[16][68];   // As[k][o] = w1[o][k]
    __shared__ float Bs[16][68];   // Bs[k][m] = points_1[b][k][m]
    const int b  = blockIdx.z;
    const int m0 = blockIdx.x * 64;
    const int o0 = blockIdx.y * 64;
    const int tid = threadIdx.x;
    const int tx = tid & 15, ty = tid >> 4;

    float acc[4][4] = {};

    for (int kc = 0; kc < CC; kc += 16) {
        for (int t = tid; t < 1024; t += 256) {
            const int o = t >> 4, k = t & 15;
            As[k][o] = w1[(o0 + o) * CC + kc + k];
        }
        for (int t = tid; t < 1024; t += 256) {
            const int k = t >> 6, m = t & 63;
            Bs[k][m] = p1in[(b * CC + kc + k) * MM + m0 + m];
        }
        __syncthreads();
        #pragma unroll
        for (int k = 0; k < 16; k++) {
            const float4 a4 = *(const float4*)&As[k][ty * 4];
            const float4 b4 = *(const float4*)&Bs[k][tx * 4];
            float ar[4] = {a4.x, a4.y, a4.z, a4.w};
            float br[4] = {b4.x, b4.y, b4.z, b4.w};
            #pragma unroll
            for (int i = 0; i < 4; i++)
                #pragma unroll
                for (int j = 0; j < 4; j++)
                    acc[i][j] = fmaf(ar[i], br[j], acc[i][j]);
        }
        __syncthreads();
    }

    const float4 bias = *(const float4*)&b1[o0 + ty * 4];
    #pragma unroll
    for (int j = 0; j < 4; j++) {
        const int m = m0 + tx * 4 + j;
        float4 v;
        v.x = acc[0][j] + bias.x;
        v.y = acc[1][j] + bias.y;
        v.z = acc[2][j] + bias.z;
        v.w = acc[3][j] + bias.w;
        *(float4*)&g_p1t[(b * MM + m) * CC + o0 + ty * 4] = v;
    }
}

// ---------------------------------------------------------------------------
// GEMM2 + fused interpolation epilogue:
// out[b][o][n] = sum_c w2[o][c]*points_2[b][c][n] + b2[o]
//               + sum_k wgt[b][n][k] * p1t[b][ idx[b][n][k] ][o]
// ---------------------------------------------------------------------------
__global__ void gemm2_kernel(const float* __restrict__ w2,
                             const float* __restrict__ b2,
                             const float* __restrict__ p2in,
                             float* __restrict__ outp) {
    __shared__ float As[16][68];   // As[k][o] = w2[o][k]
    __shared__ float Bs[16][68];   // Bs[k][n] = points_2[b][k][n]
    const int b  = blockIdx.z;
    const int n0 = blockIdx.x * 64;
    const int o0 = blockIdx.y * 64;
    const int tid = threadIdx.x;
    const int tx = tid & 15, ty = tid >> 4;

    float acc[4][4] = {};

    for (int kc = 0; kc < CC; kc += 16) {
        for (int t = tid; t < 1024; t += 256) {
            const int o = t >> 4, k = t & 15;
            As[k][o] = w2[(o0 + o) * CC + kc + k];
        }
        for (int t = tid; t < 1024; t += 256) {
            const int k = t >> 6, n = t & 63;
            Bs[k][n] = p2in[(b * CC + kc + k) * NN + n0 + n];
        }
        __syncthreads();
        #pragma unroll
        for (int k = 0; k < 16; k++) {
            const float4 a4 = *(const float4*)&As[k][ty * 4];
            const float4 b4 = *(const float4*)&Bs[k][tx * 4];
            float ar[4] = {a4.x, a4.y, a4.z, a4.w};
            float br[4] = {b4.x, b4.y, b4.z, b4.w};
            #pragma unroll
            for (int i = 0; i < 4; i++)
                #pragma unroll
                for (int j = 0; j < 4; j++)
                    acc[i][j] = fmaf(ar[i], br[j], acc[i][j]);
        }
        __syncthreads();
    }

    // Epilogue: bias + 3-NN weighted gather from p1t (o-contiguous -> float4)
    const float4 bias = *(const float4*)&b2[o0 + ty * 4];
    #pragma unroll
    for (int j = 0; j < 4; j++) {
        const int n = n0 + tx * 4 + j;
        const int base = (b * NN + n) * KK;
        const int ia = g_idx[base + 0];
        const int ib = g_idx[base + 1];
        const int ic = g_idx[base + 2];
        const float wa = g_wgt[base + 0];
        const float wb = g_wgt[base + 1];
        const float wc = g_wgt[base + 2];
        const float4 va = *(const float4*)&g_p1t[(b * MM + ia) * CC + o0 + ty * 4];
        const float4 vb = *(const float4*)&g_p1t[(b * MM + ib) * CC + o0 + ty * 4];
        const float4 vc = *(const float4*)&g_p1t[(b * MM + ic) * CC + o0 + ty * 4];
        acc[0][j] += wa * va.x + wb * vb.x + wc * vc.x;
        acc[1][j] += wa * va.y + wb * vb.y + wc * vc.y;
        acc[2][j] += wa * va.z + wb * vb.z + wc * vc.z;
        acc[3][j] += wa * va.w + wb * vb.w + wc * vc.w;
    }

    // Store: out layout [b][o][n], n contiguous per thread row
    #pragma unroll
    for (int i = 0; i < 4; i++) {
        const int o = o0 + ty * 4 + i;
        float bi = (i == 0) ? bias.x : (i == 1) ? bias.y : (i == 2) ? bias.z : bias.w;
        float4 v;
        v.x = acc[i][0] + bi;
        v.y = acc[i][1] + bi;
        v.z = acc[i][2] + bi;
        v.w = acc[i][3] + bi;
        *(float4*)&outp[((size_t)(b * CC + o)) * NN + n0 + tx * 4] = v;
    }
}

extern "C" void kernel_launch(void* const* d_in, const int* in_sizes, int n_in,
                              void* d_out, int out_size) {
    const float* xyz1 = (const float*)d_in[0];
    const float* xyz2 = (const float*)d_in[1];
    const float* p1   = (const float*)d_in[2];
    const float* p2   = (const float*)d_in[3];
    const float* w1   = (const float*)d_in[4];
    const float* b1   = (const float*)d_in[5];
    const float* w2   = (const float*)d_in[6];
    const float* b2   = (const float*)d_in[7];
    float* out = (float*)d_out;

    // Output = (xyz_2, interpolated + p2) flattened
    cudaMemcpyAsync(out, xyz2, (size_t)BB * 3 * NN * sizeof(float),
                    cudaMemcpyDeviceToDevice);

    knn_kernel<<<dim3(NN / 256, BB), 256>>>(xyz1, xyz2);
    gemm1_kernel<<<dim3(MM / 64, CC / 64, BB), 256>>>(w1, b1, p1);
    gemm2_kernel<<<dim3(NN / 64, CC / 64, BB), 256>>>(w2, b2, p2,
                                                      out + (size_t)BB * 3 * NN);
}

// round 3
// speedup vs baseline: 1.6300x; 1.6300x over previous
#include <cuda_runtime.h>
#include <float.h>

#define BB 2
#define MM 4096
#define NN 16384
#define CC 256
#define KK 3
#define CH 8
#define CHM (MM / CH)   // 512 candidates per chunk

// Scratch (no cudaMalloc allowed)
__device__ float g_p1t[BB * MM * CC];       // p1 transposed: [b][m][o], o contiguous
__device__ int   g_idx[BB * NN * KK];
__device__ float g_wgt[BB * NN * KK];
__device__ float g_pd[BB * NN * CH * KK];   // partial knn distances (surrogate)
__device__ int   g_pi[BB * NN * CH * KK];   // partial knn indices

// ---------------------------------------------------------------------------
// kNN partial: each block handles 256 queries x one 512-candidate chunk.
// Surrogate distance d = |p|^2 - 2 q.p  (same ordering as reference's
// expansion formula; |q|^2 added later in merge). 1 LDS.128 + 3 FMA per iter.
// ---------------------------------------------------------------------------
__global__ void knn_part_kernel(const float* __restrict__ xyz1,
                                const float* __restrict__ xyz2) {
    __shared__ float4 s[CHM];
    const int b = blockIdx.z;
    const int c = blockIdx.y;
    const int mbase = c * CHM;
    for (int t = threadIdx.x; t < CHM; t += 256) {
        const float x = xyz1[(b * 3 + 0) * MM + mbase + t];
        const float y = xyz1[(b * 3 + 1) * MM + mbase + t];
        const float z = xyz1[(b * 3 + 2) * MM + mbase + t];
        s[t] = make_float4(x, y, z, fmaf(x, x, fmaf(y, y, z * z)));
    }
    __syncthreads();

    const int n = blockIdx.x * 256 + threadIdx.x;
    const float ax = -2.0f * xyz2[(b * 3 + 0) * NN + n];
    const float ay = -2.0f * xyz2[(b * 3 + 1) * NN + n];
    const float az = -2.0f * xyz2[(b * 3 + 2) * NN + n];

    float d0 = FLT_MAX, d1 = FLT_MAX, d2 = FLT_MAX;
    int   i0 = 0, i1 = 0, i2 = 0;

    #pragma unroll 4
    for (int m = 0; m < CHM; m++) {
        const float4 p = s[m];
        const float d = fmaf(p.x, ax, fmaf(p.y, ay, fmaf(p.z, az, p.w)));
        if (d < d2) {
            const int gi = mbase + m;
            if (d < d1) {
                if (d < d0) { d2 = d1; i2 = i1; d1 = d0; i1 = i0; d0 = d; i0 = gi; }
                else        { d2 = d1; i2 = i1; d1 = d;  i1 = gi; }
            } else          { d2 = d;  i2 = gi; }
        }
    }

    const int base = ((b * NN + n) * CH + c) * KK;
    g_pd[base + 0] = d0; g_pd[base + 1] = d1; g_pd[base + 2] = d2;
    g_pi[base + 0] = i0; g_pi[base + 1] = i1; g_pi[base + 2] = i2;
}

// ---------------------------------------------------------------------------
// kNN merge: one thread per query merges 8 sorted top-3 partials (processed
// in chunk order -> strict '<' preserves first-occurrence tie semantics),
// then computes clamped distances and inverse-distance weights.
// ---------------------------------------------------------------------------
__global__ void knn_merge_kernel(const float* __restrict__ xyz2) {
    const int gid = blockIdx.x * 256 + threadIdx.x;   // 0 .. BB*NN-1
    const int b = gid / NN;
    const int n = gid - b * NN;

    const float qx = xyz2[(b * 3 + 0) * NN + n];
    const float qy = xyz2[(b * 3 + 1) * NN + n];
    const float qz = xyz2[(b * 3 + 2) * NN + n];
    const float qn = fmaf(qx, qx, fmaf(qy, qy, qz * qz));

    float d0 = FLT_MAX, d1 = FLT_MAX, d2 = FLT_MAX;
    int   i0 = 0, i1 = 0, i2 = 0;
    const int base = gid * CH * KK;
    #pragma unroll
    for (int t = 0; t < CH * KK; t++) {
        const float d = g_pd[base + t];
        if (d < d2) {
            const int gi = g_pi[base + t];
            if (d < d1) {
                if (d < d0) { d2 = d1; i2 = i1; d1 = d0; i1 = i0; d0 = d; i0 = gi; }
                else        { d2 = d1; i2 = i1; d1 = d;  i1 = gi; }
            } else          { d2 = d;  i2 = gi; }
        }
    }

    const float e0 = fmaxf(d0 + qn, 0.0f);
    const float e1 = fmaxf(d1 + qn, 0.0f);
    const float e2 = fmaxf(d2 + qn, 0.0f);
    const float r0 = 1.0f / (e0 + 1e-8f);
    const float r1 = 1.0f / (e1 + 1e-8f);
    const float r2 = 1.0f / (e2 + 1e-8f);
    const float sc = 1.0f / (r0 + r1 + r2);

    const int ob = gid * KK;
    g_idx[ob + 0] = i0; g_idx[ob + 1] = i1; g_idx[ob + 2] = i2;
    g_wgt[ob + 0] = r0 * sc; g_wgt[ob + 1] = r1 * sc; g_wgt[ob + 2] = r2 * sc;
}

// ---------------------------------------------------------------------------
// GEMM1: p1t[b][m][o] = sum_c w1[o][c] * points_1[b][c][m] + b1[o]
// 128(o) x 64(m) tile, 256 threads, 8x4 per thread, K-chunk 16.
// ---------------------------------------------------------------------------
__global__ __launch_bounds__(256) void gemm1_kernel(
        const float* __restrict__ w1, const float* __restrict__ b1,
        const float* __restrict__ p1in) {
    __shared__ float As[16][132];   // As[k][o]
    __shared__ float Bs[16][68];    // Bs[k][m]
    const int b  = blockIdx.z;
    const int m0 = blockIdx.x * 64;
    const int o0 = blockIdx.y * 128;
    const int tid = threadIdx.x;
    const int tx = tid & 15;        // m
    const int ty = tid >> 4;        // o

    float acc[8][4] = {};

    for (int kc = 0; kc < CC; kc += 16) {
        #pragma unroll
        for (int u = 0; u < 2; u++) {
            const int s = tid * 2 + u;          // 0..511
            const int o = s >> 2, kq = s & 3;
            const float4 w4 = *(const float4*)&w1[(o0 + o) * CC + kc + kq * 4];
            As[kq * 4 + 0][o] = w4.x; As[kq * 4 + 1][o] = w4.y;
            As[kq * 4 + 2][o] = w4.z; As[kq * 4 + 3][o] = w4.w;
        }
        {
            const int k = tid >> 4, n4 = tid & 15;
            const float4 b4 = *(const float4*)&p1in[(b * CC + kc + k) * MM + m0 + n4 * 4];
            *(float4*)&Bs[k][n4 * 4] = b4;
        }
        __syncthreads();
        #pragma unroll
        for (int k = 0; k < 16; k++) {
            const float4 a0 = *(const float4*)&As[k][ty * 8];
            const float4 a1 = *(const float4*)&As[k][ty * 8 + 4];
            const float4 bv = *(const float4*)&Bs[k][tx * 4];
            const float ar[8] = {a0.x, a0.y, a0.z, a0.w, a1.x, a1.y, a1.z, a1.w};
            const float br[4] = {bv.x, bv.y, bv.z, bv.w};
            #pragma unroll
            for (int i = 0; i < 8; i++)
                #pragma unroll
                for (int j = 0; j < 4; j++)
                    acc[i][j] = fmaf(ar[i], br[j], acc[i][j]);
        }
        __syncthreads();
    }

    const float4 bias0 = *(const float4*)&b1[o0 + ty * 8];
    const float4 bias1 = *(const float4*)&b1[o0 + ty * 8 + 4];
    const float bbv[8] = {bias0.x, bias0.y, bias0.z, bias0.w,
                          bias1.x, bias1.y, bias1.z, bias1.w};
    #pragma unroll
    for (int j = 0; j < 4; j++) {
        const int m = m0 + tx * 4 + j;
        float* dst = &g_p1t[((size_t)(b * MM + m)) * CC + o0 + ty * 8];
        float4 v0, v1;
        v0.x = acc[0][j] + bbv[0]; v0.y = acc[1][j] + bbv[1];
        v0.z = acc[2][j] + bbv[2]; v0.w = acc[3][j] + bbv[3];
        v1.x = acc[4][j] + bbv[4]; v1.y = acc[5][j] + bbv[5];
        v1.z = acc[6][j] + bbv[6]; v1.w = acc[7][j] + bbv[7];
        *(float4*)dst = v0;
        *(float4*)(dst + 4) = v1;
    }
}

// ---------------------------------------------------------------------------
// GEMM2 + fused 3-NN interpolation epilogue:
// out[b][o][n] = sum_c w2[o][c]*points_2[b][c][n] + b2[o]
//              + sum_k wgt[b][n][k] * p1t[b][idx[b][n][k]][o]
// ---------------------------------------------------------------------------
__global__ __launch_bounds__(256) void gemm2_kernel(
        const float* __restrict__ w2, const float* __restrict__ b2,
        const float* __restrict__ p2in, float* __restrict__ outp) {
    __shared__ float As[16][132];   // As[k][o]
    __shared__ float Bs[16][68];    // Bs[k][n]
    const int b  = blockIdx.z;
    const int n0 = blockIdx.x * 64;
    const int o0 = blockIdx.y * 128;
    const int tid = threadIdx.x;
    const int tx = tid & 15;        // n
    const int ty = tid >> 4;        // o

    float acc[8][4] = {};

    for (int kc = 0; kc < CC; kc += 16) {
        #pragma unroll
        for (int u = 0; u < 2; u++) {
            const int s = tid * 2 + u;
            const int o = s >> 2, kq = s & 3;
            const float4 w4 = *(const float4*)&w2[(o0 + o) * CC + kc + kq * 4];
            As[kq * 4 + 0][o] = w4.x; As[kq * 4 + 1][o] = w4.y;
            As[kq * 4 + 2][o] = w4.z; As[kq * 4 + 3][o] = w4.w;
        }
        {
            const int k = tid >> 4, n4 = tid & 15;
            const float4 b4 = *(const float4*)&p2in[((size_t)(b * CC + kc + k)) * NN + n0 + n4 * 4];
            *(float4*)&Bs[k][n4 * 4] = b4;
        }
        __syncthreads();
        #pragma unroll
        for (int k = 0; k < 16; k++) {
            const float4 a0 = *(const float4*)&As[k][ty * 8];
            const float4 a1 = *(const float4*)&As[k][ty * 8 + 4];
            const float4 bv = *(const float4*)&Bs[k][tx * 4];
            const float ar[8] = {a0.x, a0.y, a0.z, a0.w, a1.x, a1.y, a1.z, a1.w};
            const float br[4] = {bv.x, bv.y, bv.z, bv.w};
            #pragma unroll
            for (int i = 0; i < 8; i++)
                #pragma unroll
                for (int j = 0; j < 4; j++)
                    acc[i][j] = fmaf(ar[i], br[j], acc[i][j]);
        }
        __syncthreads();
    }

    // Epilogue: 3-NN weighted gather from p1t (L2-resident, o-contiguous)
    #pragma unroll
    for (int j = 0; j < 4; j++) {
        const int n = n0 + tx * 4 + j;
        const int kb = (b * NN + n) * KK;
        const int ia = g_idx[kb + 0];
        const int ib = g_idx[kb + 1];
        const int ic = g_idx[kb + 2];
        const float wa = g_wgt[kb + 0];
        const float wb = g_wgt[kb + 1];
        const float wc = g_wgt[kb + 2];
        const float* pa = &g_p1t[((size_t)(b * MM + ia)) * CC + o0 + ty * 8];
        const float* pb = &g_p1t[((size_t)(b * MM + ib)) * CC + o0 + ty * 8];
        const float* pc = &g_p1t[((size_t)(b * MM + ic)) * CC + o0 + ty * 8];
        const float4 va0 = *(const float4*)pa, va1 = *(const float4*)(pa + 4);
        const float4 vb0 = *(const float4*)pb, vb1 = *(const float4*)(pb + 4);
        const float4 vc0 = *(const float4*)pc, vc1 = *(const float4*)(pc + 4);
        acc[0][j] += wa * va0.x + wb * vb0.x + wc * vc0.x;
        acc[1][j] += wa * va0.y + wb * vb0.y + wc * vc0.y;
        acc[2][j] += wa * va0.z + wb * vb0.z + wc * vc0.z;
        acc[3][j] += wa * va0.w + wb * vb0.w + wc * vc0.w;
        acc[4][j] += wa * va1.x + wb * vb1.x + wc * vc1.x;
        acc[5][j] += wa * va1.y + wb * vb1.y + wc * vc1.y;
        acc[6][j] += wa * va1.z + wb * vb1.z + wc * vc1.z;
        acc[7][j] += wa * va1.w + wb * vb1.w + wc * vc1.w;
    }

    const float4 bias0 = *(const float4*)&b2[o0 + ty * 8];
    const float4 bias1 = *(const float4*)&b2[o0 + ty * 8 + 4];
    const float bbv[8] = {bias0.x, bias0.y, bias0.z, bias0.w,
                          bias1.x, bias1.y, bias1.z, bias1.w};
    #pragma unroll
    for (int i = 0; i < 8; i++) {
        const int o = o0 + ty * 8 + i;
        float4 v;
        v.x = acc[i][0] + bbv[i];
        v.y = acc[i][1] + bbv[i];
        v.z = acc[i][2] + bbv[i];
        v.w = acc[i][3] + bbv[i];
        *(float4*)&outp[((size_t)(b * CC + o)) * NN + n0 + tx * 4] = v;
    }
}

extern "C" void kernel_launch(void* const* d_in, const int* in_sizes, int n_in,
                              void* d_out, int out_size) {
    const float* xyz1 = (const float*)d_in[0];
    const float* xyz2 = (const float*)d_in[1];
    const float* p1   = (const float*)d_in[2];
    const float* p2   = (const float*)d_in[3];
    const float* w1   = (const float*)d_in[4];
    const float* b1   = (const float*)d_in[5];
    const float* w2   = (const float*)d_in[6];
    const float* b2   = (const float*)d_in[7];
    float* out = (float*)d_out;

    // Output = (xyz_2, interpolated + p2) flattened
    cudaMemcpyAsync(out, xyz2, (size_t)BB * 3 * NN * sizeof(float),
                    cudaMemcpyDeviceToDevice);

    knn_part_kernel<<<dim3(NN / 256, CH, BB), 256>>>(xyz1, xyz2);
    knn_merge_kernel<<<(BB * NN) / 256, 256>>>(xyz2);
    gemm1_kernel<<<dim3(MM / 64, CC / 128, BB), 256>>>(w1, b1, p1);
    gemm2_kernel<<<dim3(NN / 64, CC / 128, BB), 256>>>(w2, b2, p2,
                                                       out + (size_t)BB * 3 * NN);
}